// round 13
// baseline (speedup 1.0000x reference)
#include <cstdint>
#include <cuda_runtime.h>
#include <cuda_bf16.h>
#include <mma.h>

namespace wm = nvcuda::wmma;

// ---------------- problem constants ----------------
#define BATCH 64
#define TSTEP 32
#define EMBED 512
#define HID   1024
#define VOCAB 10000
#define FEAT  2048
#define GATES 4096           // 4*HID
#define ROWS  2048           // T*B

// ---------------- big GEMM tile config (Xg + FC) ----------------
#define BM 128
#define BN 128
#define BKT 32
#define LDS 40               // BKT + 8 pad (bf16 elems); 80B rows, 16B-aligned
#define LDC 132
#define ARR_BYTES   10240    // 128*40*2
#define STAGE_BYTES 40960    // 4 arrays
#define BIG_SMEM    81920    // 2 stages (epilogue ctile 128*132*4=67.6KB fits)

// ---------------- step kernel config ----------------
#define SN   64              // gate-cols per block (= 16 j * 4 gates)
#define SLD  40
#define SLDC 68

// ---------------- old init-GEMM config ----------------
#define OBM 64
#define OBN 128
#define OLDC 132

// ---------------- scratch (device globals; no allocations) ----------------
__device__ __align__(256) __nv_bfloat16 g_feat_hi[BATCH*FEAT],  g_feat_lo[BATCH*FEAT];
__device__ __align__(256) __nv_bfloat16 g_Wih_hi[GATES*EMBED],  g_Wih_lo[GATES*EMBED];   // PERMUTED
__device__ __align__(256) __nv_bfloat16 g_Whh_hi[GATES*HID],    g_Whh_lo[GATES*HID];     // PERMUTED
__device__ __align__(256) __nv_bfloat16 g_Wfc_hi[VOCAB*HID],    g_Wfc_lo[VOCAB*HID];
__device__ __align__(256) __nv_bfloat16 g_Wh0_hi[HID*FEAT],     g_Wh0_lo[HID*FEAT];
__device__ __align__(256) __nv_bfloat16 g_Wc0_hi[HID*FEAT],     g_Wc0_lo[HID*FEAT];
__device__ __align__(256) __nv_bfloat16 g_emb_hi[ROWS*EMBED],   g_emb_lo[ROWS*EMBED];
__device__ __align__(256) __nv_bfloat16 g_hA_hi[BATCH*HID],     g_hA_lo[BATCH*HID];      // h ping
__device__ __align__(256) __nv_bfloat16 g_hB_hi[BATCH*HID],     g_hB_lo[BATCH*HID];      // h pong
__device__ __align__(256) __nv_bfloat16 g_Hall_hi[ROWS*HID],    g_Hall_lo[ROWS*HID];
__device__ __align__(256) float g_Xg[(size_t)ROWS*GATES];       // emb@Wih^T + biases (permuted cols)
__device__ __align__(256) float g_bcomb[GATES];                 // permuted b_ih+b_hh
__device__ __align__(256) float g_c[BATCH*HID];
__device__ __align__(256) float g_part[16*BATCH*HID];           // init split-K partials

// ============================================================
// cp.async helpers
// ============================================================
__device__ __forceinline__ void cpa16(void* dst, const void* src, bool pred) {
    unsigned int s = (unsigned int)__cvta_generic_to_shared(dst);
    int sz = pred ? 16 : 0;                 // zero-fill when predicated off
    asm volatile("cp.async.cg.shared.global [%0], [%1], 16, %2;\n"
                 :: "r"(s), "l"(src), "r"(sz));
}
__device__ __forceinline__ void cp_commit() { asm volatile("cp.async.commit_group;\n"); }
template<int NW> __device__ __forceinline__ void cp_wait() {
    asm volatile("cp.async.wait_group %0;\n" :: "n"(NW));
}

// ============================================================
// Pipelined 128x128 split-bf16 GEMM:  C = A @ B^T  (+bias, opt sigmoid)
// A:[M,K] hi/lo, B:[N,K] hi/lo, K-major. M multiple of 128, K multiple of 32.
// 2-stage cp.async double buffer.
// ============================================================
__global__ __launch_bounds__(256)
void gemm128(const __nv_bfloat16* __restrict__ Ahi, const __nv_bfloat16* __restrict__ Alo,
             const __nv_bfloat16* __restrict__ Bhi, const __nv_bfloat16* __restrict__ Blo,
             int N, int K, float* __restrict__ out, const float* __restrict__ bias, int dosig)
{
    extern __shared__ char dsm[];
    const int tid = threadIdx.x;
    const int m0 = blockIdx.y * BM, n0 = blockIdx.x * BN;
    const int warp = tid >> 5, wmr = warp & 1, wnc = warp >> 1;   // 2x4 warp grid

    const __nv_bfloat16* gsrc[4] = {Ahi, Alo, Bhi, Blo};

    auto load_stage = [&](int st, int kt) {
        char* base = dsm + st * STAGE_BYTES;
#pragma unroll
        for (int arr = 0; arr < 4; arr++) {
            __nv_bfloat16* sp = (__nv_bfloat16*)(base + arr * ARR_BYTES);
#pragma unroll
            for (int i = 0; i < 2; i++) {
                int ch = tid + i * 256;                 // 512 16B chunks per array
                int r = ch >> 2, kc = (ch & 3) * 8;
                bool isB = (arr >= 2);
                int grow = (isB ? n0 : m0) + r;
                bool pred = isB ? (grow < N) : true;
                cpa16(sp + r * LDS + kc, gsrc[arr] + (size_t)grow * K + kt + kc, pred);
            }
        }
    };

    wm::fragment<wm::accumulator,16,16,16,float> acc[4][2];
#pragma unroll
    for (int i = 0; i < 4; i++)
#pragma unroll
        for (int j = 0; j < 2; j++) wm::fill_fragment(acc[i][j], 0.0f);

    const int nkt = K / BKT;
    load_stage(0, 0); cp_commit();

    for (int kt = 0; kt < nkt; kt++) {
        if (kt + 1 < nkt) { load_stage((kt + 1) & 1, (kt + 1) * BKT); cp_commit(); cp_wait<1>(); }
        else              { cp_wait<0>(); }
        __syncthreads();

        char* base = dsm + (kt & 1) * STAGE_BYTES;
        __nv_bfloat16* sAh = (__nv_bfloat16*)(base);
        __nv_bfloat16* sAl = (__nv_bfloat16*)(base +     ARR_BYTES);
        __nv_bfloat16* sBh = (__nv_bfloat16*)(base + 2 * ARR_BYTES);
        __nv_bfloat16* sBl = (__nv_bfloat16*)(base + 3 * ARR_BYTES);

#pragma unroll
        for (int kk = 0; kk < BKT; kk += 16) {
            wm::fragment<wm::matrix_a,16,16,16,__nv_bfloat16,wm::row_major> ah[4], al[4];
            wm::fragment<wm::matrix_b,16,16,16,__nv_bfloat16,wm::col_major> bh[2], bl[2];
#pragma unroll
            for (int i = 0; i < 4; i++) {
                wm::load_matrix_sync(ah[i], sAh + (wmr*64 + i*16) * LDS + kk, LDS);
                wm::load_matrix_sync(al[i], sAl + (wmr*64 + i*16) * LDS + kk, LDS);
            }
#pragma unroll
            for (int j = 0; j < 2; j++) {
                wm::load_matrix_sync(bh[j], sBh + (wnc*32 + j*16) * LDS + kk, LDS);
                wm::load_matrix_sync(bl[j], sBl + (wnc*32 + j*16) * LDS + kk, LDS);
            }
#pragma unroll
            for (int i = 0; i < 4; i++)
#pragma unroll
                for (int j = 0; j < 2; j++) {
                    wm::mma_sync(acc[i][j], ah[i], bh[j], acc[i][j]);
                    wm::mma_sync(acc[i][j], ah[i], bl[j], acc[i][j]);
                    wm::mma_sync(acc[i][j], al[i], bh[j], acc[i][j]);
                }
        }
        __syncthreads();
    }

    float* ct = (float*)dsm;
#pragma unroll
    for (int i = 0; i < 4; i++)
#pragma unroll
        for (int j = 0; j < 2; j++)
            wm::store_matrix_sync(ct + (wmr*64 + i*16) * LDC + wnc*32 + j*16,
                                  acc[i][j], LDC, wm::mem_row_major);
    __syncthreads();

    for (int s = tid; s < BM * BN; s += 256) {
        int r = s >> 7, cc = s & 127, n = n0 + cc;
        if (n >= N) continue;
        float v = ct[r * LDC + cc];
        if (bias)  v += bias[n];
        if (dosig) v = 1.0f / (1.0f + expf(-v));
        out[(size_t)(m0 + r) * N + n] = v;
    }
}

// ============================================================
// Fused LSTM step: gates tile = h @ Whh_perm^T (K=1024, 3 products),
// + pre-biased Xg, LSTM cell, write h' (hi/lo, pong buffer) + Hall row.
// Gate layout permuted: col = j*4 + gate, so one BN=64 tile holds all
// 4 gates for 16 consecutive j. Grid = 64 blocks.
// ============================================================
struct StepSmem {
    union {
        __nv_bfloat16 st[2][4][SN * SLD];   // [stage][Ahi,Alo,Bhi,Blo]
        float ct[SN * SLDC];
    };
};

__global__ __launch_bounds__(256)
void lstm_step(const __nv_bfloat16* __restrict__ hhi, const __nv_bfloat16* __restrict__ hlo,
               const __nv_bfloat16* __restrict__ Whi, const __nv_bfloat16* __restrict__ Wlo,
               const float* __restrict__ Xg_t, float* __restrict__ cst,
               __nv_bfloat16* __restrict__ ohi, __nv_bfloat16* __restrict__ olo,
               __nv_bfloat16* __restrict__ Hhi, __nv_bfloat16* __restrict__ Hlo, int t)
{
    __shared__ StepSmem sm;
    const int tid = threadIdx.x;
    const int n0 = blockIdx.x * SN;
    const int warp = tid >> 5, wmr = warp & 1, wnc = warp >> 1;   // warp tile 32(m) x 16(n)
    const __nv_bfloat16* gsrc[4] = {hhi, hlo, Whi, Wlo};

    auto load_stage = [&](int st, int kt) {
#pragma unroll
        for (int arr = 0; arr < 4; arr++) {
            int r = tid >> 2, kc = (tid & 3) * 8;     // 256 chunks = 1/thread/array
            int grow = (arr >= 2 ? n0 : 0) + r;
            cpa16(&sm.st[st][arr][r * SLD + kc], gsrc[arr] + (size_t)grow * HID + kt + kc, true);
        }
    };

    wm::fragment<wm::accumulator,16,16,16,float> acc[2];
    wm::fill_fragment(acc[0], 0.0f);
    wm::fill_fragment(acc[1], 0.0f);

    const int nkt = HID / BKT;   // 32
    load_stage(0, 0); cp_commit();

    for (int kt = 0; kt < nkt; kt++) {
        if (kt + 1 < nkt) { load_stage((kt + 1) & 1, (kt + 1) * BKT); cp_commit(); cp_wait<1>(); }
        else              { cp_wait<0>(); }
        __syncthreads();
        int s = kt & 1;
#pragma unroll
        for (int kk = 0; kk < BKT; kk += 16) {
            wm::fragment<wm::matrix_a,16,16,16,__nv_bfloat16,wm::row_major> ah[2], al[2];
            wm::fragment<wm::matrix_b,16,16,16,__nv_bfloat16,wm::col_major> bh, bl;
#pragma unroll
            for (int i = 0; i < 2; i++) {
                wm::load_matrix_sync(ah[i], &sm.st[s][0][(wmr*32 + i*16) * SLD + kk], SLD);
                wm::load_matrix_sync(al[i], &sm.st[s][1][(wmr*32 + i*16) * SLD + kk], SLD);
            }
            wm::load_matrix_sync(bh, &sm.st[s][2][(wnc*16) * SLD + kk], SLD);
            wm::load_matrix_sync(bl, &sm.st[s][3][(wnc*16) * SLD + kk], SLD);
#pragma unroll
            for (int i = 0; i < 2; i++) {
                wm::mma_sync(acc[i], ah[i], bh, acc[i]);
                wm::mma_sync(acc[i], ah[i], bl, acc[i]);
                wm::mma_sync(acc[i], al[i], bh, acc[i]);
            }
        }
        __syncthreads();
    }

#pragma unroll
    for (int i = 0; i < 2; i++)
        wm::store_matrix_sync(&sm.ct[(wmr*32 + i*16) * SLDC + wnc*16], acc[i], SLDC, wm::mem_row_major);
    __syncthreads();

    // LSTM cell: 64 b x 16 j per block = 1024 cells, 4 per thread
#pragma unroll
    for (int it = 0; it < 4; it++) {
        int idx = tid + it * 256;
        int b = idx >> 4, jl = idx & 15;
        const float* xg = Xg_t + (size_t)b * GATES + n0 + jl * 4;
        float gi = sm.ct[b * SLDC + jl*4 + 0] + xg[0];
        float gf = sm.ct[b * SLDC + jl*4 + 1] + xg[1];
        float gg = sm.ct[b * SLDC + jl*4 + 2] + xg[2];
        float go = sm.ct[b * SLDC + jl*4 + 3] + xg[3];
        float iv = 1.0f / (1.0f + expf(-gi));
        float fv = 1.0f / (1.0f + expf(-gf));
        float gv = tanhf(gg);
        float ov = 1.0f / (1.0f + expf(-go));
        int jg = (n0 >> 2) + jl;
        int ci = b * HID + jg;
        float cv = fv * cst[ci] + iv * gv;
        cst[ci] = cv;
        float hv = ov * tanhf(cv);
        __nv_bfloat16 hb = __float2bfloat16(hv);
        __nv_bfloat16 lb = __float2bfloat16(hv - __bfloat162float(hb));
        ohi[ci] = hb; olo[ci] = lb;
        size_t row = (size_t)(t * BATCH + b) * HID + jg;
        Hhi[row] = hb; Hlo[row] = lb;
    }
}

// ============================================================
// Init GEMM (small M=64, split-K)
// ============================================================
struct SmemT {
    union {
        struct {
            __nv_bfloat16 A[2][OBM * LDS];
            __nv_bfloat16 B[2][OBN * LDS];
        } s;
        float ctile[OBM * OLDC];
    };
};

__global__ __launch_bounds__(256)
void gemm_init(const __nv_bfloat16* __restrict__ Ahi, const __nv_bfloat16* __restrict__ Alo,
               const __nv_bfloat16* __restrict__ Bhi, const __nv_bfloat16* __restrict__ Blo,
               int M, int N, int K, int Kchunk, float* __restrict__ out)
{
    __shared__ SmemT sm;
    const int tid = threadIdx.x;
    const int m0 = blockIdx.y * OBM;
    const int n0 = blockIdx.x * OBN;
    const int k0 = blockIdx.z * Kchunk;
    const int warp = tid >> 5;
    const int wmr = warp & 1;
    const int wnc = warp >> 1;

    wm::fragment<wm::accumulator,16,16,16,float> c[2][2];
#pragma unroll
    for (int i=0;i<2;i++)
#pragma unroll
        for (int j=0;j<2;j++) wm::fill_fragment(c[i][j], 0.0f);

    for (int kt = 0; kt < Kchunk; kt += BKT) {
#pragma unroll
        for (int i=0;i<2;i++) {
            int s  = tid + i*256;
            int r  = s >> 3, sg = s & 7;
            size_t g = (size_t)(m0 + r)*K + (k0 + kt + sg*4);
            *reinterpret_cast<uint2*>(&sm.s.A[0][r*LDS + sg*4]) = *reinterpret_cast<const uint2*>(Ahi + g);
            *reinterpret_cast<uint2*>(&sm.s.A[1][r*LDS + sg*4]) = *reinterpret_cast<const uint2*>(Alo + g);
        }
#pragma unroll
        for (int i=0;i<4;i++) {
            int s  = tid + i*256;
            int r  = s >> 3, sg = s & 7;
            size_t g = (size_t)(n0 + r)*K + (k0 + kt + sg*4);
            *reinterpret_cast<uint2*>(&sm.s.B[0][r*LDS + sg*4]) = *reinterpret_cast<const uint2*>(Bhi + g);
            *reinterpret_cast<uint2*>(&sm.s.B[1][r*LDS + sg*4]) = *reinterpret_cast<const uint2*>(Blo + g);
        }
        __syncthreads();

#pragma unroll
        for (int kk=0; kk<BKT; kk+=16) {
            wm::fragment<wm::matrix_a,16,16,16,__nv_bfloat16,wm::row_major> ah[2], al[2];
            wm::fragment<wm::matrix_b,16,16,16,__nv_bfloat16,wm::col_major> bh[2], bl[2];
#pragma unroll
            for (int i=0;i<2;i++) {
                wm::load_matrix_sync(ah[i], &sm.s.A[0][(wmr*32+i*16)*LDS + kk], LDS);
                wm::load_matrix_sync(al[i], &sm.s.A[1][(wmr*32+i*16)*LDS + kk], LDS);
            }
#pragma unroll
            for (int j=0;j<2;j++) {
                wm::load_matrix_sync(bh[j], &sm.s.B[0][(wnc*32+j*16)*LDS + kk], LDS);
                wm::load_matrix_sync(bl[j], &sm.s.B[1][(wnc*32+j*16)*LDS + kk], LDS);
            }
#pragma unroll
            for (int i=0;i<2;i++)
#pragma unroll
                for (int j=0;j<2;j++) {
                    wm::mma_sync(c[i][j], ah[i], bh[j], c[i][j]);
                    wm::mma_sync(c[i][j], ah[i], bl[j], c[i][j]);
                    wm::mma_sync(c[i][j], al[i], bh[j], c[i][j]);
                }
        }
        __syncthreads();
    }

#pragma unroll
    for (int i=0;i<2;i++)
#pragma unroll
        for (int j=0;j<2;j++)
            wm::store_matrix_sync(&sm.ctile[(wmr*32+i*16)*OLDC + wnc*32 + j*16], c[i][j], OLDC, wm::mem_row_major);
    __syncthreads();

    float* obase = out + (size_t)blockIdx.z * M * N;
    for (int s = tid; s < OBM*OBN; s += 256) {
        int r  = s >> 7;
        int cc = s & 127;
        obase[(size_t)(m0 + r)*N + n0 + cc] = sm.ctile[r*OLDC + cc];
    }
}

// ---------------- preproc kernels (vectorized) ----------------
__device__ __forceinline__ void split_store4(__nv_bfloat16* hi, __nv_bfloat16* lo,
                                             size_t o4, float4 v)
{
    __nv_bfloat16 h0=__float2bfloat16(v.x), h1=__float2bfloat16(v.y),
                  h2=__float2bfloat16(v.z), h3=__float2bfloat16(v.w);
    __nv_bfloat16 l0=__float2bfloat16(v.x-__bfloat162float(h0));
    __nv_bfloat16 l1=__float2bfloat16(v.y-__bfloat162float(h1));
    __nv_bfloat16 l2=__float2bfloat16(v.z-__bfloat162float(h2));
    __nv_bfloat16 l3=__float2bfloat16(v.w-__bfloat162float(h3));
    __nv_bfloat162* hp = (__nv_bfloat162*)hi;
    __nv_bfloat162* lp = (__nv_bfloat162*)lo;
    __nv_bfloat162 a; a.x=h0; a.y=h1;  __nv_bfloat162 b; b.x=h2; b.y=h3;
    __nv_bfloat162 c; c.x=l0; c.y=l1;  __nv_bfloat162 d; d.x=l2; d.y=l3;
    hp[o4>>1] = a; hp[(o4>>1)+1] = b;
    lp[o4>>1] = c; lp[(o4>>1)+1] = d;
}

__global__ void split4(const float* __restrict__ x, __nv_bfloat16* __restrict__ hi,
                       __nv_bfloat16* __restrict__ lo, int n4)
{
    int i = blockIdx.x*256 + threadIdx.x;
    if (i >= n4) return;
    split_store4(hi, lo, (size_t)i*4, ((const float4*)x)[i]);
}

// split + gate-row permutation: row g = gate*1024+j  ->  j*4+gate
__global__ void split4_perm(const float* __restrict__ x, __nv_bfloat16* __restrict__ hi,
                            __nv_bfloat16* __restrict__ lo, int kshift, int n4)
{
    int i = blockIdx.x*256 + threadIdx.x;
    if (i >= n4) return;
    size_t i4 = (size_t)i*4;
    int row = (int)(i4 >> kshift);
    int col = (int)(i4 & ((1u<<kshift)-1));
    int nrow = (row & (HID-1))*4 + (row >> 10);
    split_store4(hi, lo, ((size_t)nrow << kshift) + col, ((const float4*)x)[i]);
}

__global__ void gather_emb4(const int* __restrict__ cap, const float* __restrict__ table,
                            __nv_bfloat16* __restrict__ hi, __nv_bfloat16* __restrict__ lo)
{
    int i = blockIdx.x*256 + threadIdx.x;        // over ROWS*EMBED/4
    if (i >= ROWS*EMBED/4) return;
    size_t i4 = (size_t)i*4;
    int r = (int)(i4 >> 9), col = (int)(i4 & 511);
    int t = r >> 6, b = r & 63;
    int tok = cap[b*TSTEP + t];
    float4 v = *(const float4*)(table + (size_t)tok*EMBED + col);
    split_store4(hi, lo, i4, v);
}

__global__ void bias_perm(const float* __restrict__ a, const float* __restrict__ b,
                          float* __restrict__ o)
{
    int g = blockIdx.x*256 + threadIdx.x;
    if (g >= GATES) return;
    o[(g & (HID-1))*4 + (g >> 10)] = a[g] + b[g];
}

// split-K reduce + bias, optional f32 out and/or hi/lo out
__global__ void reduce_epi(const float* __restrict__ part, int KS, int total, int N,
                           const float* __restrict__ bias, float* __restrict__ outf,
                           __nv_bfloat16* __restrict__ ohi, __nv_bfloat16* __restrict__ olo)
{
    int i = blockIdx.x*256 + threadIdx.x;
    if (i >= total) return;
    float v = 0.0f;
    for (int z = 0; z < KS; z++) v += part[(size_t)z*total + i];
    v += bias[i % N];
    if (outf) outf[i] = v;
    if (ohi) {
        __nv_bfloat16 h = __float2bfloat16(v);
        ohi[i] = h;
        olo[i] = __float2bfloat16(v - __bfloat162float(h));
    }
}

// ---------------- driver ----------------
extern "C" void kernel_launch(void* const* d_in, const int* in_sizes, int n_in,
                              void* d_out, int out_size)
{
    const float* features = (const float*)d_in[0];
    const int*   captions = (const int*)  d_in[1];
    const float* embed    = (const float*)d_in[2];
    const float* W_init_h = (const float*)d_in[3];
    const float* b_init_h = (const float*)d_in[4];
    const float* W_init_c = (const float*)d_in[5];
    const float* b_init_c = (const float*)d_in[6];
    const float* W_ih     = (const float*)d_in[7];
    const float* b_ih     = (const float*)d_in[8];
    const float* W_hh     = (const float*)d_in[9];
    const float* b_hh     = (const float*)d_in[10];
    const float* W_fc     = (const float*)d_in[11];
    const float* b_fc     = (const float*)d_in[12];
    float* out = (float*)d_out;

    auto sym = [](const void* s){ void* p=nullptr; cudaGetSymbolAddress(&p, s); return p; };
    __nv_bfloat16 *feat_hi=(__nv_bfloat16*)sym(g_feat_hi), *feat_lo=(__nv_bfloat16*)sym(g_feat_lo);
    __nv_bfloat16 *Wih_hi =(__nv_bfloat16*)sym(g_Wih_hi),  *Wih_lo =(__nv_bfloat16*)sym(g_Wih_lo);
    __nv_bfloat16 *Whh_hi =(__nv_bfloat16*)sym(g_Whh_hi),  *Whh_lo =(__nv_bfloat16*)sym(g_Whh_lo);
    __nv_bfloat16 *Wfc_hi =(__nv_bfloat16*)sym(g_Wfc_hi),  *Wfc_lo =(__nv_bfloat16*)sym(g_Wfc_lo);
    __nv_bfloat16 *Wh0_hi =(__nv_bfloat16*)sym(g_Wh0_hi),  *Wh0_lo =(__nv_bfloat16*)sym(g_Wh0_lo);
    __nv_bfloat16 *Wc0_hi =(__nv_bfloat16*)sym(g_Wc0_hi),  *Wc0_lo =(__nv_bfloat16*)sym(g_Wc0_lo);
    __nv_bfloat16 *emb_hi =(__nv_bfloat16*)sym(g_emb_hi),  *emb_lo =(__nv_bfloat16*)sym(g_emb_lo);
    __nv_bfloat16 *hA_hi  =(__nv_bfloat16*)sym(g_hA_hi),   *hA_lo  =(__nv_bfloat16*)sym(g_hA_lo);
    __nv_bfloat16 *hB_hi  =(__nv_bfloat16*)sym(g_hB_hi),   *hB_lo  =(__nv_bfloat16*)sym(g_hB_lo);
    __nv_bfloat16 *Hall_hi=(__nv_bfloat16*)sym(g_Hall_hi), *Hall_lo=(__nv_bfloat16*)sym(g_Hall_lo);
    float *Xg    =(float*)sym(g_Xg);
    float *bcomb =(float*)sym(g_bcomb);
    float *cbuf  =(float*)sym(g_c);
    float *part  =(float*)sym(g_part);

    cudaFuncSetAttribute(gemm128, cudaFuncAttributeMaxDynamicSharedMemorySize, BIG_SMEM);

    // 1) preproc: split fp32 -> bf16 hi/lo (vectorized); gate matrices permuted
    split4<<<(BATCH*FEAT/4+255)/256,256>>>(features, feat_hi, feat_lo, BATCH*FEAT/4);
    split4<<<(HID*FEAT/4+255)/256,  256>>>(W_init_h, Wh0_hi, Wh0_lo, HID*FEAT/4);
    split4<<<(HID*FEAT/4+255)/256,  256>>>(W_init_c, Wc0_hi, Wc0_lo, HID*FEAT/4);
    split4<<<(VOCAB*HID/4+255)/256, 256>>>(W_fc, Wfc_hi, Wfc_lo, VOCAB*HID/4);
    split4_perm<<<(GATES*EMBED/4+255)/256,256>>>(W_ih, Wih_hi, Wih_lo, 9,  GATES*EMBED/4);
    split4_perm<<<(GATES*HID/4+255)/256, 256>>>(W_hh, Whh_hi, Whh_lo, 10, GATES*HID/4);
    gather_emb4<<<(ROWS*EMBED/4+255)/256,256>>>(captions, embed, emb_hi, emb_lo);
    bias_perm<<<(GATES+255)/256,256>>>(b_ih, b_hh, bcomb);

    // 2) h0 / c0 (split-K=16 + deterministic reduce)
    gemm_init<<<dim3(HID/OBN, 1, 16), 256>>>(feat_hi, feat_lo, Wh0_hi, Wh0_lo,
                                             BATCH, HID, FEAT, FEAT/16, part);
    reduce_epi<<<(BATCH*HID+255)/256,256>>>(part, 16, BATCH*HID, HID, b_init_h,
                                            nullptr, hA_hi, hA_lo);
    gemm_init<<<dim3(HID/OBN, 1, 16), 256>>>(feat_hi, feat_lo, Wc0_hi, Wc0_lo,
                                             BATCH, HID, FEAT, FEAT/16, part);
    reduce_epi<<<(BATCH*HID+255)/256,256>>>(part, 16, BATCH*HID, HID, b_init_c,
                                            cbuf, nullptr, nullptr);

    // 3) Xg[T*B, 4H(perm)] = emb @ Wih_perm^T + bcomb_perm
    gemm128<<<dim3(GATES/BN, ROWS/BM, 1), 256, BIG_SMEM>>>(
        emb_hi, emb_lo, Wih_hi, Wih_lo, GATES, EMBED, Xg, bcomb, 0);

    // 4) recurrence: 32 fused step kernels, h ping-pong
    for (int t = 0; t < TSTEP; t++) {
        const __nv_bfloat16 *ihif = (t & 1) ? hB_hi : hA_hi;
        const __nv_bfloat16 *ilof = (t & 1) ? hB_lo : hA_lo;
        __nv_bfloat16 *ohif = (t & 1) ? hA_hi : hB_hi;
        __nv_bfloat16 *olof = (t & 1) ? hA_lo : hB_lo;
        lstm_step<<<GATES/SN, 256>>>(ihif, ilof, Whh_hi, Whh_lo,
                                     Xg + (size_t)t*BATCH*GATES, cbuf,
                                     ohif, olof, Hall_hi, Hall_lo, t);
    }

    // 5) out[T*B, V] = sigmoid(Hall @ Wfc^T + b_fc)
    gemm128<<<dim3((VOCAB+BN-1)/BN, ROWS/BM, 1), 256, BIG_SMEM>>>(
        Hall_hi, Hall_lo, Wfc_hi, Wfc_lo, VOCAB, HID, out, b_fc, 1);

    (void)in_sizes; (void)n_in; (void)out_size;
}